// round 14
// baseline (speedup 1.0000x reference)
#include <cuda_runtime.h>
#include <math.h>

#define Bn 512
#define Ln 64
#define En 256
#define Hn 256
#define CD 64
#define HCn 320     // H + CDIM
#define KX 512      // E + H
#define G4 1024     // 4*H
#define NEGV -1000000000.0f
#define NBLK 296    // 2 blocks/SM on 148 SMs

// ---------------- scratch (static device globals; allocation-free) ----------
__device__ float g_eg[Bn*Ln*Hn];     // e_g  [b][l][h]
__device__ float g_ep[Bn*Ln*Hn];     // e_p  [b][l][h]
__device__ float g_xhA[Bn*KX];       // [x | h] double buffer A (step parity)
__device__ float g_xhB[Bn*KX];       // [x | h] double buffer B
__device__ float g_hc[Bn*HCn];       // [h | courier]
__device__ float g_c[Bn*Hn];         // cell state, TRANSPOSED [j][b]
__device__ float g_qg[Bn*Hn];
__device__ float g_gl2[Bn*Hn];
__device__ float g_qp[Bn*Hn];
__device__ float g_Wcat[G4*KX];      // gate-interleaved: row j*4+g
__device__ float g_bcat[G4];         // gate-interleaved: [j*4+g]
__device__ float g_Wqm[Hn*HCn];      // Wq_g @ Wm   ([n][k])
__device__ float g_bqm[Hn];          // Wq_g @ bm + bq_g
__device__ unsigned char g_mask[Bn*Ln];
__device__ unsigned int g_sync;

typedef unsigned long long u64t;

__device__ __forceinline__ float sigf(float x) { return 1.0f/(1.0f+expf(-x)); }

// packed fp32x2 (per-lane IEEE fp32 FMA, bit-identical to scalar FFMA)
__device__ __forceinline__ u64t pk2(float lo, float hi) {
    u64t r; asm("mov.b64 %0, {%1, %2};" : "=l"(r) : "f"(lo), "f"(hi)); return r;
}
__device__ __forceinline__ void upk2(u64t v, float &lo, float &hi) {
    asm("mov.b64 {%0, %1}, %2;" : "=f"(lo), "=f"(hi) : "l"(v));
}
__device__ __forceinline__ u64t ffma2(u64t a, u64t b, u64t c) {
    u64t d; asm("fma.rn.f32x2 %0, %1, %2, %3;" : "=l"(d) : "l"(a), "l"(b), "l"(c));
    return d;
}

// [7/7] continued-fraction tanh (err ~1e-8 on |x|<=1; fallback beyond)
__device__ __forceinline__ float tanh_pade(float x) {
    float t = x * x;
    float num = fmaf(t, fmaf(t, (t + 378.0f), 17325.0f), 135135.0f) * x;
    float den = fmaf(t, fmaf(t, fmaf(t, 28.0f, 3150.0f), 62370.0f), 135135.0f);
    float r = __fdividef(num, den);
    if (t > 1.0f) r = tanhf(x);
    return r;
}

// ---------------- grid barrier ----------------------------------------------
__device__ __forceinline__ void gbar(unsigned int &cnt) {
    __syncthreads();
    cnt += gridDim.x;
    if (threadIdx.x == 0) {
        __threadfence();
        atomicAdd(&g_sync, 1u);
        while (*(volatile unsigned int*)&g_sync < cnt) { }
        __threadfence();
    }
    __syncthreads();
}

// ---------------- P1: fused gates GEMM + LSTM, gate-interleaved W -----------
// Tile: 32 batches x 64 interleaved cols (= 16 j x 4 gates). 256 jobs.
// Thread: batch=lane, cols w8..w8+7 = 2 j x 4 gates. Inner: 1 LDS.32 + 2 LDS.128
// + 4 ffma2. Per-output k-order identical to R13 -> bit-exact.
__device__ void gates_lstm(const float* __restrict__ xh_rd, float* __restrict__ xh_wr,
                           char* sm)
{
    float (*sA)[16][32] = (float (*)[16][32])sm;            // 4 KB
    float (*sW)[16][64] = (float (*)[16][64])(sm + 4096);   // 8 KB
    const int tid = threadIdx.x;
    const int lane = tid & 31;           // batch within tile
    const int warp = tid >> 5;
    const int w8 = warp << 3;            // this thread's 8-col group
    const int job = blockIdx.x;
    if (job >= 256) { __syncthreads(); return; }
    const int m0 = (job & 15) << 5;      // 16 m-tiles of 32 batches
    const int n0 = (job >> 4) << 6;      // 16 n-tiles of 64 interleaved cols
    const int j0 = n0 >> 2;              // j base (16 j per tile)
    const bool aAct = tid < 128;
    const int ar = tid >> 2, ak = (tid & 3) << 2;
    const int wn = tid >> 2, wk = (tid & 3) << 2;           // wn 0..63

    const float* Ap = xh_rd + (size_t)(m0 + ar) * KX + ak;
    const float* Wp = g_Wcat + (size_t)(n0 + wn) * KX + wk;
    float4 ra, rw;
    if (aAct) ra = *(const float4*)Ap;
    rw = *(const float4*)Wp;
    u64t acc[4] = {0ull,0ull,0ull,0ull};
    __syncthreads();
    int buf = 0;
    for (int k0 = 0; k0 < KX; k0 += 16) {
        if (aAct) {
            sA[buf][ak+0][ar]=ra.x; sA[buf][ak+1][ar]=ra.y;
            sA[buf][ak+2][ar]=ra.z; sA[buf][ak+3][ar]=ra.w;
        }
        sW[buf][wk+0][wn]=rw.x; sW[buf][wk+1][wn]=rw.y;
        sW[buf][wk+2][wn]=rw.z; sW[buf][wk+3][wn]=rw.w;
        __syncthreads();
        if (k0 + 16 < KX) {
            if (aAct) ra = *(const float4*)(Ap + k0 + 16);
            rw = *(const float4*)(Wp + k0 + 16);
        }
        #pragma unroll
        for (int kk = 0; kk < 16; kk++) {
            const float a = sA[buf][kk][lane];
            const u64t ap = pk2(a, a);
            const ulonglong2 w0 = *(const ulonglong2*)&sW[buf][kk][w8];
            const ulonglong2 w1 = *(const ulonglong2*)&sW[buf][kk][w8 + 4];
            acc[0] = ffma2(ap, w0.x, acc[0]);
            acc[1] = ffma2(ap, w0.y, acc[1]);
            acc[2] = ffma2(ap, w1.x, acc[2]);
            acc[3] = ffma2(ap, w1.y, acc[3]);
        }
        buf ^= 1;
    }
    // acc[0]=(I,F) j; acc[1]=(G,O) j; acc[2]=(I,F) j+1; acc[3]=(G,O) j+1
    const int b = m0 + lane;
    #pragma unroll
    for (int r = 0; r < 2; r++) {
        const int j = j0 + (warp << 1) + r;
        float I, F, G, O;
        upk2(acc[r*2 + 0], I, F);
        upk2(acc[r*2 + 1], G, O);
        float i_ = sigf(I + g_bcat[(j<<2) + 0]);
        float f_ = sigf(F + g_bcat[(j<<2) + 1]);
        float gg = tanhf(G + g_bcat[(j<<2) + 2]);
        float o_ = sigf(O + g_bcat[(j<<2) + 3]);
        float c = f_ * g_c[(size_t)j*Bn + b] + i_ * gg;
        float h = o_ * tanhf(c);
        g_c[(size_t)j*Bn + b]         = c;
        xh_wr[(size_t)b*KX + En + j]  = h;    // next step's gates input
        g_hc[(size_t)b*HCn + j]       = h;    // this step's qg input
    }
}

// ---------------- small GEMM: 8x64 tiles, 256 jobs (R4-verified body) -------
template<int K>
__device__ void gemm_phase8(const float* __restrict__ A, const float* __restrict__ W,
                            const float* __restrict__ bias, float* __restrict__ C,
                            char* sm)
{
    float (*sA)[16][8]  = (float (*)[16][8])sm;             // 1 KB
    float (*sW)[16][64] = (float (*)[16][64])(sm + 1024);   // 8 KB
    const int tid = threadIdx.x;
    const int job = blockIdx.x;
    if (job >= 256) { __syncthreads(); return; }
    const int m0 = (job & 63) << 3;         // 64 m-tiles
    const int n0 = (job >> 6) << 6;         // 4 n-tiles
    const int tr = tid >> 5;                // 0..7 output row
    const int tc = tid & 31;                // cols 2tc, 2tc+1
    const bool aAct = tid < 32;
    const int am = tid >> 2;                // 0..7
    const int ak = (tid & 3) << 2;
    const int wn = tid >> 2;                // 0..63
    const int wk = (tid & 3) << 2;

    const float* Arow = A + (size_t)(m0 + am) * K + ak;
    const float* Wrow = W + (size_t)(n0 + wn) * K + wk;
    float4 ra, rw;
    if (aAct) ra = *(const float4*)Arow;
    rw = *(const float4*)Wrow;
    float acc0 = 0.f, acc1 = 0.f;
    __syncthreads();
    int buf = 0;
    for (int k0 = 0; k0 < K; k0 += 16) {
        if (aAct) {
            sA[buf][ak+0][am]=ra.x; sA[buf][ak+1][am]=ra.y;
            sA[buf][ak+2][am]=ra.z; sA[buf][ak+3][am]=ra.w;
        }
        sW[buf][wk+0][wn]=rw.x; sW[buf][wk+1][wn]=rw.y;
        sW[buf][wk+2][wn]=rw.z; sW[buf][wk+3][wn]=rw.w;
        __syncthreads();
        if (k0 + 16 < K) {
            if (aAct) ra = *(const float4*)(Arow + k0 + 16);
            rw = *(const float4*)(Wrow + k0 + 16);
        }
        #pragma unroll
        for (int kk = 0; kk < 16; kk++) {
            const float a = sA[buf][kk][tr];
            const float2 w = *(const float2*)&sW[buf][kk][tc << 1];
            acc0 = fmaf(a, w.x, acc0);
            acc1 = fmaf(a, w.y, acc1);
        }
        buf ^= 1;
    }
    const int nc = n0 + (tc << 1);
    *(float2*)(C + (size_t)(m0+tr)*Hn + nc) =
        make_float2(acc0 + bias[nc], acc1 + bias[nc+1]);
}

// ---------------- one-time: Wqm = Wq_g @ Wm, bqm = Wq_g@bm + bq_g -----------
__global__ void wqm_kernel(const float* __restrict__ Wm, const float* __restrict__ bm,
                           const float* __restrict__ Wqg, const float* __restrict__ bqg)
{
    __shared__ float sq[256];
    const int n = blockIdx.x;
    const int k = threadIdx.x;
    if (k < 256) sq[k] = Wqg[n*256 + k];
    __syncthreads();
    float acc = 0.f;
    for (int h = 0; h < 256; h++)
        acc = fmaf(sq[h], Wm[(size_t)h*HCn + k], acc);
    g_Wqm[(size_t)n*HCn + k] = acc;
    if (k == 0) {
        float s = 0.f;
        for (int h = 0; h < 256; h++) s = fmaf(sq[h], bm[h], s);
        g_bqm[n] = s + bqg[n];
    }
}

// ---------------- one-time e GEMM v2 (R13-verified) -------------------------
__global__ __launch_bounds__(256) void gemm_e2(
    const float* __restrict__ A,
    const float* __restrict__ Wg, const float* __restrict__ bg,
    const float* __restrict__ Wp, const float* __restrict__ bp,
    float* __restrict__ Cg, float* __restrict__ Cp)
{
    __shared__ float sA[2][16][64];
    __shared__ float sWg[2][16][64];
    __shared__ float sWp[2][16][64];
    __shared__ float stg[32 * 68];
    const int tid = threadIdx.x;
    const int lane = tid & 31;
    const int w8 = (tid >> 5) << 3;
    const int ar = tid >> 2;
    const int ak = (tid & 3) << 2;

    const int job = blockIdx.x;
    const int m0 = (job & 511) << 6;
    const int n0 = (job >> 9) << 6;
    const int mrow = m0 + ar;
    const int arow = (mrow & 63) * Bn + (mrow >> 6);
    const float* Ap  = A  + (size_t)arow * Hn + ak;
    const float* Wgp = Wg + (size_t)(n0 + ar) * Hn + ak;
    const float* Wpp = Wp + (size_t)(n0 + ar) * Hn + ak;

    float4 ra  = *(const float4*)Ap;
    float4 rwg = *(const float4*)Wgp;
    float4 rwp = *(const float4*)Wpp;
    u64t ag[8]  = {0ull,0ull,0ull,0ull,0ull,0ull,0ull,0ull};
    u64t app[8] = {0ull,0ull,0ull,0ull,0ull,0ull,0ull,0ull};
    int buf = 0;
    for (int k0 = 0; k0 < Hn; k0 += 16) {
        sA [buf][ak+0][ar]=ra.x;  sA [buf][ak+1][ar]=ra.y;
        sA [buf][ak+2][ar]=ra.z;  sA [buf][ak+3][ar]=ra.w;
        sWg[buf][ak+0][ar]=rwg.x; sWg[buf][ak+1][ar]=rwg.y;
        sWg[buf][ak+2][ar]=rwg.z; sWg[buf][ak+3][ar]=rwg.w;
        sWp[buf][ak+0][ar]=rwp.x; sWp[buf][ak+1][ar]=rwp.y;
        sWp[buf][ak+2][ar]=rwp.z; sWp[buf][ak+3][ar]=rwp.w;
        __syncthreads();
        if (k0 + 16 < Hn) {
            ra  = *(const float4*)(Ap  + k0 + 16);
            rwg = *(const float4*)(Wgp + k0 + 16);
            rwp = *(const float4*)(Wpp + k0 + 16);
        }
        #pragma unroll
        for (int kk = 0; kk < 16; kk++) {
            const float a0 = sA[buf][kk][lane];
            const float a1 = sA[buf][kk][lane + 32];
            const u64t ap0 = pk2(a0, a0);
            const u64t ap1 = pk2(a1, a1);
            const ulonglong2 g0 = *(const ulonglong2*)&sWg[buf][kk][w8];
            const ulonglong2 g1 = *(const ulonglong2*)&sWg[buf][kk][w8 + 4];
            const ulonglong2 p0 = *(const ulonglong2*)&sWp[buf][kk][w8];
            const ulonglong2 p1 = *(const ulonglong2*)&sWp[buf][kk][w8 + 4];
            ag[0]  = ffma2(ap0, g0.x, ag[0]);
            ag[1]  = ffma2(ap0, g0.y, ag[1]);
            ag[2]  = ffma2(ap0, g1.x, ag[2]);
            ag[3]  = ffma2(ap0, g1.y, ag[3]);
            ag[4]  = ffma2(ap1, g0.x, ag[4]);
            ag[5]  = ffma2(ap1, g0.y, ag[5]);
            ag[6]  = ffma2(ap1, g1.x, ag[6]);
            ag[7]  = ffma2(ap1, g1.y, ag[7]);
            app[0] = ffma2(ap0, p0.x, app[0]);
            app[1] = ffma2(ap0, p0.y, app[1]);
            app[2] = ffma2(ap0, p1.x, app[2]);
            app[3] = ffma2(ap0, p1.y, app[3]);
            app[4] = ffma2(ap1, p0.x, app[4]);
            app[5] = ffma2(ap1, p0.y, app[5]);
            app[6] = ffma2(ap1, p1.x, app[6]);
            app[7] = ffma2(ap1, p1.y, app[7]);
        }
        buf ^= 1;
    }
    const int row = tid >> 3;
    const int col = (tid & 7) << 3;
    #pragma unroll
    for (int s = 0; s < 2; s++) {
        const u64t* acc = s ? app : ag;
        const float* bias = s ? bp : bg;
        float* C = s ? Cp : Cg;
        #pragma unroll
        for (int hh = 0; hh < 2; hh++) {
            float r[8];
            upk2(acc[hh*4+0], r[0], r[1]); upk2(acc[hh*4+1], r[2], r[3]);
            upk2(acc[hh*4+2], r[4], r[5]); upk2(acc[hh*4+3], r[6], r[7]);
            __syncthreads();
            *(float4*)&stg[lane*68 + w8]     = make_float4(r[0], r[1], r[2], r[3]);
            *(float4*)&stg[lane*68 + w8 + 4] = make_float4(r[4], r[5], r[6], r[7]);
            __syncthreads();
            float4 v0 = *(const float4*)&stg[row*68 + col];
            float4 v1 = *(const float4*)&stg[row*68 + col + 4];
            const float4 b0 = *(const float4*)(bias + n0 + col);
            const float4 b1 = *(const float4*)(bias + n0 + col + 4);
            float* Cr = C + (size_t)(m0 + hh*32 + row) * Hn + n0 + col;
            *(float4*)Cr       = make_float4(v0.x+b0.x, v0.y+b0.y, v0.z+b0.z, v0.w+b0.w);
            *(float4*)(Cr + 4) = make_float4(v1.x+b1.x, v1.y+b1.y, v1.z+b1.z, v1.w+b1.w);
        }
    }
}

// ---------------- one-time setup (gate-interleaved Wcat/bcat) ---------------
__global__ void setup_kernel(
    const float* __restrict__ dec, const float* __restrict__ h0,
    const float* __restrict__ c0, const float* __restrict__ courier,
    const unsigned char* __restrict__ im,
    const float* __restrict__ W_ih, const float* __restrict__ W_hh,
    const float* __restrict__ b_ih, const float* __restrict__ b_hh)
{
    int i = blockIdx.x * blockDim.x + threadIdx.x;
    if (i == 0) g_sync = 0;
    if (i < G4*KX) {
        int n = i / KX, k = i % KX;
        int j = n >> 2, g = n & 3;               // interleaved row j*4+g
        int orow = g * 256 + j;                  // original gate-major row
        g_Wcat[i] = (k < En) ? W_ih[orow*En + k] : W_hh[orow*Hn + (k - En)];
    }
    if (i < G4) {
        int j = i >> 2, g = i & 3;
        int orow = g * 256 + j;
        g_bcat[i] = b_ih[orow] + b_hh[orow];
    }
    if (i < Bn*KX) {
        int b = i / KX, j = i % KX;
        g_xhA[i] = (j < En) ? dec[b*En + j] : h0[b*Hn + (j - En)];
    }
    if (i < Bn*Hn) {                     // transposed c: g_c[j*Bn + b]
        int b = i % Bn, j = i / Bn;
        g_c[i] = c0[b*Hn + j];
    }
    if (i < Bn*CD) {
        int b = i / CD, j = i % CD;
        g_hc[b*HCn + Hn + j] = courier[i];
    }
    if (i < Bn*Ln) g_mask[i] = im[i];
}

// ---------------- the persistent decoder kernel (5 phases/step) -------------
__global__ __launch_bounds__(256, 2) void persist_kernel(
    const float* __restrict__ emb,
    const float* __restrict__ Wq_p, const float* __restrict__ bq_p,
    const float* __restrict__ v_g,  const float* __restrict__ v_p,
    float* __restrict__ out)
{
    extern __shared__ char smc[];                // 64 KB: e-tile / GEMM buffers
    float* es = (float*)smc;
    __shared__ float qs[256], vs[256], wv[64];
    __shared__ float s_mx, s_ls;
    __shared__ int   s_sel;

    const int t = threadIdx.x;
    const int warp = t >> 5, lane = t & 31;
    unsigned int barcnt = 0;

    for (int step = 0; step < Ln; step++) {
        const float* xh_rd = (step & 1) ? g_xhB : g_xhA;
        float*       xh_wr = (step & 1) ? g_xhA : g_xhB;

        // ---- P1: gates GEMM + LSTM pointwise (fused, interleaved W) ----
        gates_lstm(xh_rd, xh_wr, smc);
        gbar(barcnt);

        // ---- P2: qg = [h|courier] @ Wqm^T + bqm  (K=320, 8x64 tiles) ----
        gemm_phase8<HCn>(g_hc, g_Wqm, g_bqm, g_qg, smc);
        gbar(barcnt);

        // ---- P3: attention g (scores + softmax + weighted sum) ----
        for (int b = blockIdx.x; b < Bn; b += gridDim.x) {
            __syncthreads();
            const float4* src = (const float4*)(g_eg + (size_t)b * Ln * Hn);
            float4* d4 = (float4*)es;
            #pragma unroll
            for (int i = t; i < 4096; i += 256) d4[i] = src[i];
            qs[t] = g_qg[b*Hn + t];
            vs[t] = v_g[t];
            __syncthreads();

            #pragma unroll
            for (int l0 = 0; l0 < 64; l0 += 8) {
                int l = l0 + warp;
                const float* row = es + l * 256;
                float acc = 0.f;
                #pragma unroll
                for (int j = 0; j < 8; j++) {
                    int h = lane + 32*j;
                    acc += vs[h] * tanh_pade(qs[h] + row[h]);
                }
                #pragma unroll
                for (int o = 16; o; o >>= 1) acc += __shfl_xor_sync(0xffffffffu, acc, o);
                if (lane == 0) wv[l] = g_mask[b*Ln + l] ? NEGV : acc;
            }
            __syncthreads();

            if (warp == 0) {
                float a = wv[lane], c = wv[lane + 32];
                float m = fmaxf(a, c);
                #pragma unroll
                for (int o = 16; o; o >>= 1) m = fmaxf(m, __shfl_xor_sync(0xffffffffu, m, o));
                float ea = expf(a - m), ec = expf(c - m);
                float s = ea + ec;
                #pragma unroll
                for (int o = 16; o; o >>= 1) s += __shfl_xor_sync(0xffffffffu, s, o);
                wv[lane]      = ea / s;
                wv[lane + 32] = ec / s;
            }
            __syncthreads();

            float acc = 0.f;
            #pragma unroll
            for (int l = 0; l < 64; l++) acc += es[l*256 + t] * wv[l];
            g_gl2[b*Hn + t] = acc;
        }
        gbar(barcnt);

        // ---- P4: qp = gl2 @ Wq_p^T + bq_p  (8x64 tiles) ----
        gemm_phase8<Hn>(g_gl2, Wq_p, bq_p, g_qp, smc);
        gbar(barcnt);

        // ---- P5: attention p (log-softmax + argmax + mask + gather) ----
        for (int b = blockIdx.x; b < Bn; b += gridDim.x) {
            __syncthreads();
            const float4* src = (const float4*)(g_ep + (size_t)b * Ln * Hn);
            float4* d4 = (float4*)es;
            #pragma unroll
            for (int i = t; i < 4096; i += 256) d4[i] = src[i];
            qs[t] = g_qp[b*Hn + t];
            vs[t] = v_p[t];
            __syncthreads();

            #pragma unroll
            for (int l0 = 0; l0 < 64; l0 += 8) {
                int l = l0 + warp;
                const float* row = es + l * 256;
                float acc = 0.f;
                #pragma unroll
                for (int j = 0; j < 8; j++) {
                    int h = lane + 32*j;
                    acc += vs[h] * tanh_pade(qs[h] + row[h]);
                }
                #pragma unroll
                for (int o = 16; o; o >>= 1) acc += __shfl_xor_sync(0xffffffffu, acc, o);
                if (lane == 0) wv[l] = g_mask[b*Ln + l] ? NEGV : (10.0f * tanhf(acc));
            }
            __syncthreads();

            if (warp == 0) {
                float a = wv[lane], c = wv[lane + 32];
                float m = fmaxf(a, c);
                #pragma unroll
                for (int o = 16; o; o >>= 1) m = fmaxf(m, __shfl_xor_sync(0xffffffffu, m, o));
                float s = expf(a - m) + expf(c - m);
                #pragma unroll
                for (int o = 16; o; o >>= 1) s += __shfl_xor_sync(0xffffffffu, s, o);
                float bv = a; int bi = lane;
                if (c > bv) { bv = c; bi = lane + 32; }
                #pragma unroll
                for (int o = 16; o; o >>= 1) {
                    float ov = __shfl_xor_sync(0xffffffffu, bv, o);
                    int   oi = __shfl_xor_sync(0xffffffffu, bi, o);
                    if (ov > bv || (ov == bv && oi < bi)) { bv = ov; bi = oi; }
                }
                if (lane == 0) {
                    s_mx = m; s_ls = logf(s); s_sel = bi;
                    unsigned char* mk = g_mask + b*Ln;
                    mk[bi] = 1;
                    int cnt = 0;
                    #pragma unroll
                    for (int l = 0; l < Ln; l++) cnt += mk[l];
                    if (cnt == Ln) mk[Ln - 1] = 0;
                    out[(size_t)(Bn*Ln*Ln) + (size_t)b*Ln + step] = (float)bi;
                }
            }
            __syncthreads();

            if (t < Ln)
                out[(size_t)b*Ln*Ln + (size_t)step*Ln + t] = wv[t] - s_mx - s_ls;

            int sel = s_sel;
            xh_wr[(size_t)b*KX + t] = emb[((size_t)sel*Bn + b)*En + t];
        }
        gbar(barcnt);
    }
}

// ---------------- host ----------------
extern "C" void kernel_launch(void* const* d_in, const int* in_sizes, int n_in,
                              void* d_out, int out_size)
{
    const float* dec     = (const float*)d_in[0];
    const float* emb     = (const float*)d_in[1];
    const float* h0      = (const float*)d_in[2];
    const float* c0      = (const float*)d_in[3];
    const float* ctx     = (const float*)d_in[4];
    const float* courier = (const float*)d_in[5];
    const unsigned char* initm = (const unsigned char*)d_in[6];
    const float* W_ih = (const float*)d_in[7];
    const float* W_hh = (const float*)d_in[8];
    const float* b_ih = (const float*)d_in[9];
    const float* b_hh = (const float*)d_in[10];
    const float* Wm   = (const float*)d_in[11];
    const float* bm   = (const float*)d_in[12];
    const float* Wq_p = (const float*)d_in[13];
    const float* bq_p = (const float*)d_in[14];
    const float* Wr_p = (const float*)d_in[15];
    const float* br_p = (const float*)d_in[16];
    const float* v_p  = (const float*)d_in[17];
    const float* Wq_g = (const float*)d_in[18];
    const float* bq_g = (const float*)d_in[19];
    const float* Wr_g = (const float*)d_in[20];
    const float* br_g = (const float*)d_in[21];
    const float* v_g  = (const float*)d_in[22];
    float* out = (float*)d_out;

    cudaFuncSetAttribute(persist_kernel, cudaFuncAttributeMaxDynamicSharedMemorySize, 65536);

    float *eg, *ep;
    cudaGetSymbolAddress((void**)&eg, g_eg);
    cudaGetSymbolAddress((void**)&ep, g_ep);

    setup_kernel<<<1024, 512>>>(dec, h0, c0, courier, initm, W_ih, W_hh, b_ih, b_hh);
    wqm_kernel<<<256, 320>>>(Wm, bm, Wq_g, bq_g);

    // e_g / e_p = context @ Wr^T + br, stored [b][l][h] — both in one pass
    gemm_e2<<<2048, 256>>>(ctx, Wr_g, br_g, Wr_p, br_p, eg, ep);

    persist_kernel<<<NBLK, 256, 65536>>>(emb, Wq_p, bq_p, v_g, v_p, out);
}

// round 17
// speedup vs baseline: 1.6937x; 1.6937x over previous
#include <cuda_runtime.h>
#include <math.h>

#define Bn 512
#define Ln 64
#define En 256
#define Hn 256
#define CD 64
#define HCn 320     // H + CDIM
#define KX 512      // E + H
#define G4 1024     // 4*H
#define NEGV -1000000000.0f
#define NBLK 296    // 2 blocks/SM on 148 SMs

// ---------------- scratch (static device globals; allocation-free) ----------
__device__ float g_eg[Bn*Ln*Hn];     // e_g  [b][l][h]
__device__ float g_ep[Bn*Ln*Hn];     // e_p  [b][l][h]
__device__ float g_xhA[Bn*KX];       // [x | h] double buffer A (step parity)
__device__ float g_xhB[Bn*KX];       // [x | h] double buffer B
__device__ float g_hc[Bn*HCn];       // [h | courier]
__device__ float g_c[Bn*Hn];         // cell state, TRANSPOSED [j][b]
__device__ float g_qg[Bn*Hn];
__device__ float g_gl2[Bn*Hn];
__device__ float g_qp[Bn*Hn];
__device__ float g_Wcat[G4*KX];      // gate-interleaved: row j*4+g
__device__ float g_bcat[G4];         // gate-interleaved: [j*4+g]
__device__ float g_Wqm[Hn*HCn];      // Wq_g @ Wm   ([n][k])
__device__ float g_bqm[Hn];          // Wq_g @ bm + bq_g
__device__ unsigned char g_mask[Bn*Ln];
__device__ unsigned int g_sync;

typedef unsigned long long u64t;

__device__ __forceinline__ float sigf(float x) { return 1.0f/(1.0f+expf(-x)); }

// packed fp32x2 (per-lane IEEE fp32 FMA, bit-identical to scalar FFMA)
__device__ __forceinline__ u64t pk2(float lo, float hi) {
    u64t r; asm("mov.b64 %0, {%1, %2};" : "=l"(r) : "f"(lo), "f"(hi)); return r;
}
__device__ __forceinline__ void upk2(u64t v, float &lo, float &hi) {
    asm("mov.b64 {%0, %1}, %2;" : "=f"(lo), "=f"(hi) : "l"(v));
}
__device__ __forceinline__ u64t ffma2(u64t a, u64t b, u64t c) {
    u64t d; asm("fma.rn.f32x2 %0, %1, %2, %3;" : "=l"(d) : "l"(a), "l"(b), "l"(c));
    return d;
}

// [7/7] continued-fraction tanh (err ~1e-8 on |x|<=1; fallback beyond)
__device__ __forceinline__ float tanh_pade(float x) {
    float t = x * x;
    float num = fmaf(t, fmaf(t, (t + 378.0f), 17325.0f), 135135.0f) * x;
    float den = fmaf(t, fmaf(t, fmaf(t, 28.0f, 3150.0f), 62370.0f), 135135.0f);
    float r = __fdividef(num, den);
    if (t > 1.0f) r = tanhf(x);
    return r;
}

// ---------------- grid barrier ----------------------------------------------
__device__ __forceinline__ void gbar(unsigned int &cnt) {
    __syncthreads();
    cnt += gridDim.x;
    if (threadIdx.x == 0) {
        __threadfence();
        atomicAdd(&g_sync, 1u);
        while (*(volatile unsigned int*)&g_sync < cnt) { }
        __threadfence();
    }
    __syncthreads();
}

// ---------------- P1: fused gates GEMM + LSTM, gate-interleaved W -----------
// Tile: 32 batches x 64 interleaved cols (= 16 j x 4 gates). 256 jobs.
// Thread: batch=lane, cols w8..w8+7 = 2 j x 4 gates. Inner: 1 LDS.32 + 2 LDS.128
// + 4 ffma2. Per-output k-order identical to R13 -> bit-exact.
__device__ void gates_lstm(const float* __restrict__ xh_rd, float* __restrict__ xh_wr,
                           char* sm)
{
    float (*sA)[16][32] = (float (*)[16][32])sm;            // 4 KB
    float (*sW)[16][64] = (float (*)[16][64])(sm + 4096);   // 8 KB
    const int tid = threadIdx.x;
    const int lane = tid & 31;           // batch within tile
    const int warp = tid >> 5;
    const int w8 = warp << 3;            // this thread's 8-col group
    const int job = blockIdx.x;
    if (job >= 256) { __syncthreads(); return; }
    const int m0 = (job & 15) << 5;      // 16 m-tiles of 32 batches
    const int n0 = (job >> 4) << 6;      // 16 n-tiles of 64 interleaved cols
    const int j0 = n0 >> 2;              // j base (16 j per tile)
    const bool aAct = tid < 128;
    const int ar = tid >> 2, ak = (tid & 3) << 2;
    const int wn = tid >> 2, wk = (tid & 3) << 2;           // wn 0..63

    const float* Ap = xh_rd + (size_t)(m0 + ar) * KX + ak;
    const float* Wp = g_Wcat + (size_t)(n0 + wn) * KX + wk;
    float4 ra, rw;
    if (aAct) ra = *(const float4*)Ap;
    rw = *(const float4*)Wp;
    u64t acc[4] = {0ull,0ull,0ull,0ull};
    __syncthreads();
    int buf = 0;
    for (int k0 = 0; k0 < KX; k0 += 16) {
        if (aAct) {
            sA[buf][ak+0][ar]=ra.x; sA[buf][ak+1][ar]=ra.y;
            sA[buf][ak+2][ar]=ra.z; sA[buf][ak+3][ar]=ra.w;
        }
        sW[buf][wk+0][wn]=rw.x; sW[buf][wk+1][wn]=rw.y;
        sW[buf][wk+2][wn]=rw.z; sW[buf][wk+3][wn]=rw.w;
        __syncthreads();
        if (k0 + 16 < KX) {
            if (aAct) ra = *(const float4*)(Ap + k0 + 16);
            rw = *(const float4*)(Wp + k0 + 16);
        }
        #pragma unroll
        for (int kk = 0; kk < 16; kk++) {
            const float a = sA[buf][kk][lane];
            const u64t ap = pk2(a, a);
            const ulonglong2 w0 = *(const ulonglong2*)&sW[buf][kk][w8];
            const ulonglong2 w1 = *(const ulonglong2*)&sW[buf][kk][w8 + 4];
            acc[0] = ffma2(ap, w0.x, acc[0]);
            acc[1] = ffma2(ap, w0.y, acc[1]);
            acc[2] = ffma2(ap, w1.x, acc[2]);
            acc[3] = ffma2(ap, w1.y, acc[3]);
        }
        buf ^= 1;
    }
    // acc[0]=(I,F) j; acc[1]=(G,O) j; acc[2]=(I,F) j+1; acc[3]=(G,O) j+1
    const int b = m0 + lane;
    #pragma unroll
    for (int r = 0; r < 2; r++) {
        const int j = j0 + (warp << 1) + r;
        float I, F, G, O;
        upk2(acc[r*2 + 0], I, F);
        upk2(acc[r*2 + 1], G, O);
        float i_ = sigf(I + g_bcat[(j<<2) + 0]);
        float f_ = sigf(F + g_bcat[(j<<2) + 1]);
        float gg = tanhf(G + g_bcat[(j<<2) + 2]);
        float o_ = sigf(O + g_bcat[(j<<2) + 3]);
        float c = f_ * g_c[(size_t)j*Bn + b] + i_ * gg;
        float h = o_ * tanhf(c);
        g_c[(size_t)j*Bn + b]         = c;
        xh_wr[(size_t)b*KX + En + j]  = h;    // next step's gates input
        g_hc[(size_t)b*HCn + j]       = h;    // this step's qg input
    }
}

// ---------------- small GEMM phase (R13-verified, TM=16, 128 jobs) ----------
template<int TM>
__device__ void gemm_phase(const float* __restrict__ A, const float* __restrict__ W,
                           const float* __restrict__ bias, float* __restrict__ C,
                           int M, int N, int K,
                           float (*sA)[16][32], float (*sW)[16][64])
{
    const int tid = threadIdx.x;
    const int tm = tid >> 4;
    const int tn = tid & 15;
    const int mt = M / TM, nt = N >> 6;
    const int njobs = mt * nt;
    const bool aAct = tid < TM * 4;
    const int am = tid >> 2;
    const int ak = (tid & 3) << 2;
    const int wn = tid >> 2;
    const int wk = (tid & 3) << 2;

    for (int job = blockIdx.x; job < njobs; job += gridDim.x) {
        const int m0 = (job % mt) * TM;
        const int n0 = (job / mt) << 6;
        const float* Arow = A + (size_t)(m0 + am) * K + ak;
        const float* Wrow = W + (size_t)(n0 + wn) * K + wk;
        float4 ra, rw;
        if (aAct) ra = *(const float4*)(Arow);
        rw = *(const float4*)(Wrow);
        float acc0[4] = {0,0,0,0};
        __syncthreads();
        int buf = 0;
        for (int k0 = 0; k0 < K; k0 += 16) {
            if (aAct) {
                sA[buf][ak+0][am] = ra.x; sA[buf][ak+1][am] = ra.y;
                sA[buf][ak+2][am] = ra.z; sA[buf][ak+3][am] = ra.w;
            }
            sW[buf][wk+0][wn] = rw.x; sW[buf][wk+1][wn] = rw.y;
            sW[buf][wk+2][wn] = rw.z; sW[buf][wk+3][wn] = rw.w;
            __syncthreads();
            if (k0 + 16 < K) {
                if (aAct) ra = *(const float4*)(Arow + k0 + 16);
                rw = *(const float4*)(Wrow + k0 + 16);
            }
            #pragma unroll
            for (int kk = 0; kk < 16; kk++) {
                const float4 w = *(const float4*)&sW[buf][kk][tn << 2];
                const float a0 = sA[buf][kk][tm];
                acc0[0] = fmaf(a0, w.x, acc0[0]);
                acc0[1] = fmaf(a0, w.y, acc0[1]);
                acc0[2] = fmaf(a0, w.z, acc0[2]);
                acc0[3] = fmaf(a0, w.w, acc0[3]);
            }
            buf ^= 1;
        }
        const int nc = n0 + (tn << 2);
        float b0 = bias[nc], b1 = bias[nc+1], b2 = bias[nc+2], b3 = bias[nc+3];
        float* Cr = C + (size_t)(m0 + tm) * N + nc;
        Cr[0] = acc0[0] + b0; Cr[1] = acc0[1] + b1;
        Cr[2] = acc0[2] + b2; Cr[3] = acc0[3] + b3;
    }
}

// ---------------- one-time: Wqm = Wq_g @ Wm, bqm = Wq_g@bm + bq_g -----------
__global__ void wqm_kernel(const float* __restrict__ Wm, const float* __restrict__ bm,
                           const float* __restrict__ Wqg, const float* __restrict__ bqg)
{
    __shared__ float sq[256];
    const int n = blockIdx.x;
    const int k = threadIdx.x;
    if (k < 256) sq[k] = Wqg[n*256 + k];
    __syncthreads();
    float acc = 0.f;
    for (int h = 0; h < 256; h++)
        acc = fmaf(sq[h], Wm[(size_t)h*HCn + k], acc);
    g_Wqm[(size_t)n*HCn + k] = acc;
    if (k == 0) {
        float s = 0.f;
        for (int h = 0; h < 256; h++) s = fmaf(sq[h], bm[h], s);
        g_bqm[n] = s + bqg[n];
    }
}

// ---------------- one-time e GEMM v2 (R13-verified) -------------------------
__global__ __launch_bounds__(256) void gemm_e2(
    const float* __restrict__ A,
    const float* __restrict__ Wg, const float* __restrict__ bg,
    const float* __restrict__ Wp, const float* __restrict__ bp,
    float* __restrict__ Cg, float* __restrict__ Cp)
{
    __shared__ float sA[2][16][64];
    __shared__ float sWg[2][16][64];
    __shared__ float sWp[2][16][64];
    __shared__ float stg[32 * 68];
    const int tid = threadIdx.x;
    const int lane = tid & 31;
    const int w8 = (tid >> 5) << 3;
    const int ar = tid >> 2;
    const int ak = (tid & 3) << 2;

    const int job = blockIdx.x;
    const int m0 = (job & 511) << 6;
    const int n0 = (job >> 9) << 6;
    const int mrow = m0 + ar;
    const int arow = (mrow & 63) * Bn + (mrow >> 6);
    const float* Ap  = A  + (size_t)arow * Hn + ak;
    const float* Wgp = Wg + (size_t)(n0 + ar) * Hn + ak;
    const float* Wpp = Wp + (size_t)(n0 + ar) * Hn + ak;

    float4 ra  = *(const float4*)Ap;
    float4 rwg = *(const float4*)Wgp;
    float4 rwp = *(const float4*)Wpp;
    u64t ag[8]  = {0ull,0ull,0ull,0ull,0ull,0ull,0ull,0ull};
    u64t app[8] = {0ull,0ull,0ull,0ull,0ull,0ull,0ull,0ull};
    int buf = 0;
    for (int k0 = 0; k0 < Hn; k0 += 16) {
        sA [buf][ak+0][ar]=ra.x;  sA [buf][ak+1][ar]=ra.y;
        sA [buf][ak+2][ar]=ra.z;  sA [buf][ak+3][ar]=ra.w;
        sWg[buf][ak+0][ar]=rwg.x; sWg[buf][ak+1][ar]=rwg.y;
        sWg[buf][ak+2][ar]=rwg.z; sWg[buf][ak+3][ar]=rwg.w;
        sWp[buf][ak+0][ar]=rwp.x; sWp[buf][ak+1][ar]=rwp.y;
        sWp[buf][ak+2][ar]=rwp.z; sWp[buf][ak+3][ar]=rwp.w;
        __syncthreads();
        if (k0 + 16 < Hn) {
            ra  = *(const float4*)(Ap  + k0 + 16);
            rwg = *(const float4*)(Wgp + k0 + 16);
            rwp = *(const float4*)(Wpp + k0 + 16);
        }
        #pragma unroll
        for (int kk = 0; kk < 16; kk++) {
            const float a0 = sA[buf][kk][lane];
            const float a1 = sA[buf][kk][lane + 32];
            const u64t ap0 = pk2(a0, a0);
            const u64t ap1 = pk2(a1, a1);
            const ulonglong2 g0 = *(const ulonglong2*)&sWg[buf][kk][w8];
            const ulonglong2 g1 = *(const ulonglong2*)&sWg[buf][kk][w8 + 4];
            const ulonglong2 p0 = *(const ulonglong2*)&sWp[buf][kk][w8];
            const ulonglong2 p1 = *(const ulonglong2*)&sWp[buf][kk][w8 + 4];
            ag[0]  = ffma2(ap0, g0.x, ag[0]);
            ag[1]  = ffma2(ap0, g0.y, ag[1]);
            ag[2]  = ffma2(ap0, g1.x, ag[2]);
            ag[3]  = ffma2(ap0, g1.y, ag[3]);
            ag[4]  = ffma2(ap1, g0.x, ag[4]);
            ag[5]  = ffma2(ap1, g0.y, ag[5]);
            ag[6]  = ffma2(ap1, g1.x, ag[6]);
            ag[7]  = ffma2(ap1, g1.y, ag[7]);
            app[0] = ffma2(ap0, p0.x, app[0]);
            app[1] = ffma2(ap0, p0.y, app[1]);
            app[2] = ffma2(ap0, p1.x, app[2]);
            app[3] = ffma2(ap0, p1.y, app[3]);
            app[4] = ffma2(ap1, p0.x, app[4]);
            app[5] = ffma2(ap1, p0.y, app[5]);
            app[6] = ffma2(ap1, p1.x, app[6]);
            app[7] = ffma2(ap1, p1.y, app[7]);
        }
        buf ^= 1;
    }
    const int row = tid >> 3;
    const int col = (tid & 7) << 3;
    #pragma unroll
    for (int s = 0; s < 2; s++) {
        const u64t* acc = s ? app : ag;
        const float* bias = s ? bp : bg;
        float* C = s ? Cp : Cg;
        #pragma unroll
        for (int hh = 0; hh < 2; hh++) {
            float r[8];
            upk2(acc[hh*4+0], r[0], r[1]); upk2(acc[hh*4+1], r[2], r[3]);
            upk2(acc[hh*4+2], r[4], r[5]); upk2(acc[hh*4+3], r[6], r[7]);
            __syncthreads();
            *(float4*)&stg[lane*68 + w8]     = make_float4(r[0], r[1], r[2], r[3]);
            *(float4*)&stg[lane*68 + w8 + 4] = make_float4(r[4], r[5], r[6], r[7]);
            __syncthreads();
            float4 v0 = *(const float4*)&stg[row*68 + col];
            float4 v1 = *(const float4*)&stg[row*68 + col + 4];
            const float4 b0 = *(const float4*)(bias + n0 + col);
            const float4 b1 = *(const float4*)(bias + n0 + col + 4);
            float* Cr = C + (size_t)(m0 + hh*32 + row) * Hn + n0 + col;
            *(float4*)Cr       = make_float4(v0.x+b0.x, v0.y+b0.y, v0.z+b0.z, v0.w+b0.w);
            *(float4*)(Cr + 4) = make_float4(v1.x+b1.x, v1.y+b1.y, v1.z+b1.z, v1.w+b1.w);
        }
    }
}

// ---------------- one-time setup (gate-interleaved Wcat/bcat) ---------------
__global__ void setup_kernel(
    const float* __restrict__ dec, const float* __restrict__ h0,
    const float* __restrict__ c0, const float* __restrict__ courier,
    const unsigned char* __restrict__ im,
    const float* __restrict__ W_ih, const float* __restrict__ W_hh,
    const float* __restrict__ b_ih, const float* __restrict__ b_hh)
{
    int i = blockIdx.x * blockDim.x + threadIdx.x;
    if (i == 0) g_sync = 0;
    if (i < G4*KX) {
        int n = i / KX, k = i % KX;
        int j = n >> 2, g = n & 3;               // interleaved row j*4+g
        int orow = g * 256 + j;                  // original gate-major row
        g_Wcat[i] = (k < En) ? W_ih[orow*En + k] : W_hh[orow*Hn + (k - En)];
    }
    if (i < G4) {
        int j = i >> 2, g = i & 3;
        int orow = g * 256 + j;
        g_bcat[i] = b_ih[orow] + b_hh[orow];
    }
    if (i < Bn*KX) {
        int b = i / KX, j = i % KX;
        g_xhA[i] = (j < En) ? dec[b*En + j] : h0[b*Hn + (j - En)];
    }
    if (i < Bn*Hn) {                     // transposed c: g_c[j*Bn + b]
        int b = i % Bn, j = i / Bn;
        g_c[i] = c0[b*Hn + j];
    }
    if (i < Bn*CD) {
        int b = i / CD, j = i % CD;
        g_hc[b*HCn + Hn + j] = courier[i];
    }
    if (i < Bn*Ln) g_mask[i] = im[i];
}

// ---------------- the persistent decoder kernel (5 phases/step) -------------
__global__ __launch_bounds__(256, 2) void persist_kernel(
    const float* __restrict__ emb,
    const float* __restrict__ Wq_p, const float* __restrict__ bq_p,
    const float* __restrict__ v_g,  const float* __restrict__ v_p,
    float* __restrict__ out)
{
    extern __shared__ char smc[];                // 64 KB: e-tile / GEMM buffers
    float* es = (float*)smc;
    float (*sAg)[16][32] = (float (*)[16][32])smc;
    float (*sWg)[16][64] = (float (*)[16][64])(smc + 4096);
    __shared__ float qs[256], vs[256], wv[64];
    __shared__ float s_mx, s_ls;
    __shared__ int   s_sel;

    const int t = threadIdx.x;
    const int warp = t >> 5, lane = t & 31;
    unsigned int barcnt = 0;

    for (int step = 0; step < Ln; step++) {
        const float* xh_rd = (step & 1) ? g_xhB : g_xhA;
        float*       xh_wr = (step & 1) ? g_xhA : g_xhB;

        // ---- P1: gates GEMM + LSTM pointwise (fused, interleaved W) ----
        gates_lstm(xh_rd, xh_wr, smc);
        gbar(barcnt);

        // ---- P2: qg = [h|courier] @ Wqm^T + bqm  (K=320, 16x64 tiles) ----
        gemm_phase<16>(g_hc, g_Wqm, g_bqm, g_qg, Bn, Hn, HCn, sAg, sWg);
        gbar(barcnt);

        // ---- P3: attention g (scores + softmax + weighted sum) ----
        for (int b = blockIdx.x; b < Bn; b += gridDim.x) {
            __syncthreads();
            const float4* src = (const float4*)(g_eg + (size_t)b * Ln * Hn);
            float4* d4 = (float4*)es;
            #pragma unroll
            for (int i = t; i < 4096; i += 256) d4[i] = src[i];
            qs[t] = g_qg[b*Hn + t];
            vs[t] = v_g[t];
            __syncthreads();

            #pragma unroll
            for (int l0 = 0; l0 < 64; l0 += 8) {
                int l = l0 + warp;
                const float* row = es + l * 256;
                float acc = 0.f;
                #pragma unroll
                for (int j = 0; j < 8; j++) {
                    int h = lane + 32*j;
                    acc += vs[h] * tanh_pade(qs[h] + row[h]);
                }
                #pragma unroll
                for (int o = 16; o; o >>= 1) acc += __shfl_xor_sync(0xffffffffu, acc, o);
                if (lane == 0) wv[l] = g_mask[b*Ln + l] ? NEGV : acc;
            }
            __syncthreads();

            if (warp == 0) {
                float a = wv[lane], c = wv[lane + 32];
                float m = fmaxf(a, c);
                #pragma unroll
                for (int o = 16; o; o >>= 1) m = fmaxf(m, __shfl_xor_sync(0xffffffffu, m, o));
                float ea = expf(a - m), ec = expf(c - m);
                float s = ea + ec;
                #pragma unroll
                for (int o = 16; o; o >>= 1) s += __shfl_xor_sync(0xffffffffu, s, o);
                wv[lane]      = ea / s;
                wv[lane + 32] = ec / s;
            }
            __syncthreads();

            float acc = 0.f;
            #pragma unroll
            for (int l = 0; l < 64; l++) acc += es[l*256 + t] * wv[l];
            g_gl2[b*Hn + t] = acc;
        }
        gbar(barcnt);

        // ---- P4: qp = gl2 @ Wq_p^T + bq_p  (16x64 tiles) ----
        gemm_phase<16>(g_gl2, Wq_p, bq_p, g_qp, Bn, Hn, Hn, sAg, sWg);
        gbar(barcnt);

        // ---- P5: attention p (log-softmax + argmax + mask + gather) ----
        for (int b = blockIdx.x; b < Bn; b += gridDim.x) {
            __syncthreads();
            const float4* src = (const float4*)(g_ep + (size_t)b * Ln * Hn);
            float4* d4 = (float4*)es;
            #pragma unroll
            for (int i = t; i < 4096; i += 256) d4[i] = src[i];
            qs[t] = g_qp[b*Hn + t];
            vs[t] = v_p[t];
            __syncthreads();

            #pragma unroll
            for (int l0 = 0; l0 < 64; l0 += 8) {
                int l = l0 + warp;
                const float* row = es + l * 256;
                float acc = 0.f;
                #pragma unroll
                for (int j = 0; j < 8; j++) {
                    int h = lane + 32*j;
                    acc += vs[h] * tanh_pade(qs[h] + row[h]);
                }
                #pragma unroll
                for (int o = 16; o; o >>= 1) acc += __shfl_xor_sync(0xffffffffu, acc, o);
                if (lane == 0) wv[l] = g_mask[b*Ln + l] ? NEGV : (10.0f * tanhf(acc));
            }
            __syncthreads();

            if (warp == 0) {
                float a = wv[lane], c = wv[lane + 32];
                float m = fmaxf(a, c);
                #pragma unroll
                for (int o = 16; o; o >>= 1) m = fmaxf(m, __shfl_xor_sync(0xffffffffu, m, o));
                float s = expf(a - m) + expf(c - m);
                #pragma unroll
                for (int o = 16; o; o >>= 1) s += __shfl_xor_sync(0xffffffffu, s, o);
                float bv = a; int bi = lane;
                if (c > bv) { bv = c; bi = lane + 32; }
                #pragma unroll
                for (int o = 16; o; o >>= 1) {
                    float ov = __shfl_xor_sync(0xffffffffu, bv, o);
                    int   oi = __shfl_xor_sync(0xffffffffu, bi, o);
                    if (ov > bv || (ov == bv && oi < bi)) { bv = ov; bi = oi; }
                }
                if (lane == 0) {
                    s_mx = m; s_ls = logf(s); s_sel = bi;
                    unsigned char* mk = g_mask + b*Ln;
                    mk[bi] = 1;
                    int cnt = 0;
                    #pragma unroll
                    for (int l = 0; l < Ln; l++) cnt += mk[l];
                    if (cnt == Ln) mk[Ln - 1] = 0;
                    out[(size_t)(Bn*Ln*Ln) + (size_t)b*Ln + step] = (float)bi;
                }
            }
            __syncthreads();

            if (t < Ln)
                out[(size_t)b*Ln*Ln + (size_t)step*Ln + t] = wv[t] - s_mx - s_ls;

            int sel = s_sel;
            xh_wr[(size_t)b*KX + t] = emb[((size_t)sel*Bn + b)*En + t];
        }
        gbar(barcnt);
    }
}

// ---------------- host ----------------
extern "C" void kernel_launch(void* const* d_in, const int* in_sizes, int n_in,
                              void* d_out, int out_size)
{
    const float* dec     = (const float*)d_in[0];
    const float* emb     = (const float*)d_in[1];
    const float* h0      = (const float*)d_in[2];
    const float* c0      = (const float*)d_in[3];
    const float* ctx     = (const float*)d_in[4];
    const float* courier = (const float*)d_in[5];
    const unsigned char* initm = (const unsigned char*)d_in[6];
    const float* W_ih = (const float*)d_in[7];
    const float* W_hh = (const float*)d_in[8];
    const float* b_ih = (const float*)d_in[9];
    const float* b_hh = (const float*)d_in[10];
    const float* Wm   = (const float*)d_in[11];
    const float* bm   = (const float*)d_in[12];
    const float* Wq_p = (const float*)d_in[13];
    const float* bq_p = (const float*)d_in[14];
    const float* Wr_p = (const float*)d_in[15];
    const float* br_p = (const float*)d_in[16];
    const float* v_p  = (const float*)d_in[17];
    const float* Wq_g = (const float*)d_in[18];
    const float* bq_g = (const float*)d_in[19];
    const float* Wr_g = (const float*)d_in[20];
    const float* br_g = (const float*)d_in[21];
    const float* v_g  = (const float*)d_in[22];
    float* out = (float*)d_out;

    cudaFuncSetAttribute(persist_kernel, cudaFuncAttributeMaxDynamicSharedMemorySize, 65536);

    float *eg, *ep;
    cudaGetSymbolAddress((void**)&eg, g_eg);
    cudaGetSymbolAddress((void**)&ep, g_ep);

    setup_kernel<<<1024, 512>>>(dec, h0, c0, courier, initm, W_ih, W_hh, b_ih, b_hh);
    wqm_kernel<<<256, 320>>>(Wm, bm, Wq_g, bq_g);

    // e_g / e_p = context @ Wr^T + br, stored [b][l][h] — both in one pass
    gemm_e2<<<2048, 256>>>(ctx, Wr_g, br_g, Wr_p, br_p, eg, ep);

    persist_kernel<<<NBLK, 256, 65536>>>(emb, Wq_p, bq_p, v_g, v_p, out);
}